// round 12
// baseline (speedup 1.0000x reference)
#include <cuda_runtime.h>
#include <cuda_fp16.h>
#include <cstdint>

#define N_NODES 2048
#define N_EDGES 16384
#define B_DIM 8
#define C_DIM 64
#define T_DIM 12
#define BT 96                 // B*T
#define OUT_DIM 64

// ---------------- scratch (static __device__, no allocation) ----------------
__device__ float  g_h2[N_NODES * BT * C_DIM];    // h * log2(e) fp32, [n][bt][c]
__device__ __half g_hH[N_NODES * BT * C_DIM];    // h * log2(e) fp16 (gather copy)
// feats pre-split to bf16 hi/lo, pre-SW128-swizzled per 128B row: [bt][n][128B]
__device__ __align__(16) uint8_t g_fh[BT * N_NODES * 128];
__device__ __align__(16) uint8_t g_fl[BT * N_NODES * 128];
// W^T pre-split bf16 hi/lo, pre-swizzled: [o][128B]
__device__ __align__(16) uint8_t g_wh[OUT_DIM * 128];
__device__ __align__(16) uint8_t g_wl[OUT_DIM * 128];
__device__ int   g_cnt[N_NODES];                 // zeroed by k_gemm_mma (post-msg)
__device__ int   g_epack[N_NODES * 64];          // (eid<<11)|src per dst slot

// ---------------- packed f32x2 helpers ----------------
union F2U { float2 f; unsigned long long u; };
__device__ __forceinline__ float2 f2add(float2 a, float2 b) {
    F2U A, B2, D; A.f = a; B2.f = b;
    asm("add.rn.f32x2 %0, %1, %2;" : "=l"(D.u) : "l"(A.u), "l"(B2.u));
    return D.f;
}
__device__ __forceinline__ float2 f2fma(float2 a, float2 b, float2 c) {
    F2U A, B2, C2, D; A.f = a; B2.f = b; C2.f = c;
    asm("fma.rn.f32x2 %0, %1, %2, %3;" : "=l"(D.u) : "l"(A.u), "l"(B2.u), "l"(C2.u));
    return D.f;
}
__device__ __forceinline__ float ex2f(float x) {
    float r; asm("ex2.approx.f32 %0, %1;" : "=f"(r) : "f"(x)); return r;
}
__device__ __forceinline__ float rcpf(float x) {
    float r; asm("rcp.approx.f32 %0, %1;" : "=f"(r) : "f"(x)); return r;
}
__device__ __forceinline__ uint32_t smem_u32(const void* p) {
    uint32_t a;
    asm("{ .reg .u64 t; cvta.to.shared.u64 t, %1; cvt.u32.u64 %0, t; }"
        : "=r"(a) : "l"(p));
    return a;
}
// split two fp32 into packed bf16x2 hi + lo (hi = rn(x), lo = rn(x - hi))
__device__ __forceinline__ void bf16_split2(float a, float b,
                                            uint32_t& hp, uint32_t& lp) {
    asm("cvt.rn.bf16x2.f32 %0, %1, %2;" : "=r"(hp) : "f"(b), "f"(a));
    float fa = __uint_as_float(hp << 16);
    float fb = __uint_as_float(hp & 0xffff0000u);
    float ra = a - fa, rb = b - fb;
    asm("cvt.rn.bf16x2.f32 %0, %1, %2;" : "=r"(lp) : "f"(rb), "f"(ra));
}
#define SW128(off) ((off) ^ (((off) >> 3) & 0x70))

// ---------------- stage A: transpose [B,C,T,N] -> [N,BT,C] (*log2e), fp32+fp16.
// Extra z-slice (z==BT): by==0 -> edge bucket build; by==1,bx==0 -> W prep. --
__global__ void k_transpose(const float* __restrict__ nf,
                            const float* __restrict__ W,
                            const int* __restrict__ src,
                            const int* __restrict__ dst) {
    if (blockIdx.z == BT) {
        int t = threadIdx.y * 32 + threadIdx.x;
        if (blockIdx.y == 0) {
            // bucket-place edges (g_cnt is zero: static init / zeroed by gemm)
            int e = blockIdx.x * 256 + t;      // 64 blocks x 256 = 16384
            int d = dst[e];
            int p = atomicAdd(&g_cnt[d], 1);
            g_epack[(d << 6) + p] = (e << 11) | src[e];
        } else if (blockIdx.x == 0) {
            // W^T bf16 hi/lo, SW128-swizzled rows
            for (int i = t; i < 2048; i += 256) {   // i = o*32 + cp
                int o = i >> 5, cp = i & 31;
                float w0 = W[(2 * cp) * 64 + o];
                float w1 = W[(2 * cp + 1) * 64 + o];
                uint32_t hp, lp;
                bf16_split2(w0, w1, hp, lp);
                uint32_t off = SW128((uint32_t)(o * 128 + cp * 4));
                *(uint32_t*)(g_wh + off) = hp;
                *(uint32_t*)(g_wl + off) = lp;
            }
        }
        return;
    }
    __shared__ float tile[32][33];
    const float LOG2E = 1.4426950408889634f;
    int bt = blockIdx.z;
    int b = bt / T_DIM, t = bt - b * T_DIM;
    int c0 = blockIdx.y << 5, n0 = blockIdx.x << 5;
    int tx = threadIdx.x, ty = threadIdx.y;
#pragma unroll
    for (int i = 0; i < 4; i++) {
        int c = c0 + ty + i * 8;
        tile[ty + i * 8][tx] =
            nf[(((b * C_DIM + c) * T_DIM + t) * N_NODES) + n0 + tx] * LOG2E;
    }
    __syncthreads();
#pragma unroll
    for (int i = 0; i < 4; i++) {
        int n = n0 + ty + i * 8;
        float v = tile[tx][ty + i * 8];
        int idx = ((n * BT + bt) << 6) + c0 + tx;
        g_h2[idx] = v;
        g_hH[idx] = __float2half_rn(v);
    }
}

// ---------------- stage B: message + softmax + agg + residual ---------------
// grid (N_NODES, 3), block 256: co = tid&7 (c-octet), grp = tid>>3 (32 bt).
// h gathered in fp16 (half traffic); e staged fp32 in smem; accum fp32.
// No max-pass needed: r = relu(.)*log2e in [0,~16], 2^r cannot overflow.
#define MSG_BT 32
__global__ __launch_bounds__(256) void k_msg(const float* __restrict__ ef) {
    __shared__ __align__(16) float s_ev[64 * 64];
    __shared__ int s_ep[64];
    __shared__ int s_cnt;
    int n = blockIdx.x;
    int tid = threadIdx.x;
    if (tid == 0) s_cnt = g_cnt[n];
    if (tid < 64) s_ep[tid] = g_epack[(n << 6) + tid];
    __syncthreads();
    int cnt = s_cnt;
    const float LOG2E = 1.4426950408889634f;
    for (int i = tid; i < (cnt << 6); i += 256) {
        int eid = s_ep[i >> 6] >> 11;
        s_ev[i] = ef[(eid << 6) + (i & 63)] * LOG2E;
    }
    __syncthreads();

    int co = tid & 7;             // c-octet: c = 8*co .. +7
    int grp = tid >> 3;           // bt slot 0..31
    int bt = blockIdx.y * MSG_BT + grp;

    float2 den[4], num[4];
#pragma unroll
    for (int i = 0; i < 4; i++) {
        den[i] = make_float2(0.f, 0.f);
        num[i] = make_float2(0.f, 0.f);
    }

    const float4* evp4 = (const float4*)s_ev;      // [edge][16 float4]
    const uint4* hb = (const uint4*)g_hH;          // row = 8 uint4 (64 halves)

#define PROC8(HV, EA, EB)                                                  \
    {                                                                      \
        float2 f0 = __half22float2(*(const __half2*)&(HV).x);              \
        float2 f1 = __half22float2(*(const __half2*)&(HV).y);              \
        float2 f2 = __half22float2(*(const __half2*)&(HV).z);              \
        float2 f3 = __half22float2(*(const __half2*)&(HV).w);              \
        float2 v0 = f2add(f0, make_float2((EA).x, (EA).y));                \
        float2 v1 = f2add(f1, make_float2((EA).z, (EA).w));                \
        float2 v2 = f2add(f2, make_float2((EB).x, (EB).y));                \
        float2 v3 = f2add(f3, make_float2((EB).z, (EB).w));                \
        float2 r0 = make_float2(fmaxf(v0.x, 0.f), fmaxf(v0.y, 0.f));       \
        float2 r1 = make_float2(fmaxf(v1.x, 0.f), fmaxf(v1.y, 0.f));       \
        float2 r2 = make_float2(fmaxf(v2.x, 0.f), fmaxf(v2.y, 0.f));       \
        float2 r3 = make_float2(fmaxf(v3.x, 0.f), fmaxf(v3.y, 0.f));       \
        float2 p0 = make_float2(ex2f(r0.x), ex2f(r0.y));                   \
        float2 p1 = make_float2(ex2f(r1.x), ex2f(r1.y));                   \
        float2 p2 = make_float2(ex2f(r2.x), ex2f(r2.y));                   \
        float2 p3 = make_float2(ex2f(r3.x), ex2f(r3.y));                   \
        den[0] = f2add(den[0], p0); num[0] = f2fma(r0, p0, num[0]);        \
        den[1] = f2add(den[1], p1); num[1] = f2fma(r1, p1, num[1]);        \
        den[2] = f2add(den[2], p2); num[2] = f2fma(r2, p2, num[2]);        \
        den[3] = f2add(den[3], p3); num[3] = f2fma(r3, p3, num[3]);        \
    }

    int k = 0;
    for (; k + 2 <= cnt; k += 2) {
        int s0 = s_ep[k] & 2047;
        int s1 = s_ep[k + 1] & 2047;
        uint4 hv0 = hb[(s0 * BT + bt) * 8 + co];
        uint4 hv1 = hb[(s1 * BT + bt) * 8 + co];
        float4 ea0 = evp4[(k << 4) + (co << 1)];
        float4 eb0 = evp4[(k << 4) + (co << 1) + 1];
        float4 ea1 = evp4[((k + 1) << 4) + (co << 1)];
        float4 eb1 = evp4[((k + 1) << 4) + (co << 1) + 1];
        PROC8(hv0, ea0, eb0);
        PROC8(hv1, ea1, eb1);
    }
    if (k < cnt) {
        int s0 = s_ep[k] & 2047;
        uint4 hv0 = hb[(s0 * BT + bt) * 8 + co];
        float4 ea0 = evp4[(k << 4) + (co << 1)];
        float4 eb0 = evp4[(k << 4) + (co << 1) + 1];
        PROC8(hv0, ea0, eb0);
    }
#undef PROC8

    const float LN2 = 0.6931471805599453f;
    const float EPS = 1e-7f;
    // residual h (fp32) for this thread's 8 c's
    const float4* hq = (const float4*)(g_h2 + ((n * BT + bt) << 6)) + (co << 1);
    float4 ha = hq[0], hc = hq[1];
    float2 hp[4] = {{ha.x, ha.y}, {ha.z, ha.w}, {hc.x, hc.y}, {hc.z, hc.w}};

    uint32_t H[4], L[4];
    bool has = (cnt > 0);
#pragma unroll
    for (int i = 0; i < 4; i++) {
        float2 agg = make_float2(0.f, 0.f);
        if (has) {
            agg.x = fmaf(num[i].x * rcpf(den[i].x), LN2, EPS);
            agg.y = fmaf(num[i].y * rcpf(den[i].y), LN2, EPS);
        }
        float ox = fmaf(hp[i].x, LN2, agg.x);
        float oy = fmaf(hp[i].y, LN2, agg.y);
        bf16_split2(ox, oy, H[i], L[i]);
    }
    size_t base = ((size_t)bt * N_NODES + n) * 128 +
                  (((uint32_t)(co * 16)) ^ (((uint32_t)n & 7) << 4));
    *(uint4*)(g_fh + base) = make_uint4(H[0], H[1], H[2], H[3]);
    *(uint4*)(g_fl + base) = make_uint4(L[0], L[1], L[2], L[3]);
}

// ---------------- stage C: HMMA bf16 GEMM (mma.sync), out [B,O,T,N] ---------
// Also zeroes g_cnt for the next launch (runs after k_msg consumed it).
#define SM_AH 0
#define SM_AL 16384
#define SM_BH 32768
#define SM_BL 40960

__device__ __forceinline__ void ldsm4(uint32_t* r, uint32_t addr) {
    asm volatile("ldmatrix.sync.aligned.m8n8.x4.shared.b16 {%0,%1,%2,%3}, [%4];"
                 : "=r"(r[0]), "=r"(r[1]), "=r"(r[2]), "=r"(r[3]) : "r"(addr));
}
__device__ __forceinline__ void mma16816(float* d, const uint32_t* a,
                                         uint32_t b0, uint32_t b1) {
    asm volatile(
        "mma.sync.aligned.m16n8k16.row.col.f32.bf16.bf16.f32 "
        "{%0,%1,%2,%3}, {%4,%5,%6,%7}, {%8,%9}, {%0,%1,%2,%3};"
        : "+f"(d[0]), "+f"(d[1]), "+f"(d[2]), "+f"(d[3])
        : "r"(a[0]), "r"(a[1]), "r"(a[2]), "r"(a[3]), "r"(b0), "r"(b1));
}

__global__ __launch_bounds__(128) void k_gemm_mma(const float* __restrict__ bias,
                                                  float* __restrict__ out) {
    __shared__ __align__(1024) uint8_t smem[49152];
    uint32_t sb = smem_u32(smem);
    int tid = threadIdx.x;
    int bt = blockIdx.y;
    int n0 = blockIdx.x << 7;

    if (bt == 0) g_cnt[(blockIdx.x << 7) + tid] = 0;   // 16*128 = 2048

    // ---- prologue: pure coalesced copies (pre-swizzled in gmem) ----
    {
        const uint4* sH = (const uint4*)(g_fh + ((size_t)bt * N_NODES + n0) * 128);
        const uint4* sL = (const uint4*)(g_fl + ((size_t)bt * N_NODES + n0) * 128);
        uint4* dH = (uint4*)(smem + SM_AH);
        uint4* dL = (uint4*)(smem + SM_AL);
#pragma unroll
        for (int i = 0; i < 8; i++) {
            dH[tid + i * 128] = sH[tid + i * 128];
            dL[tid + i * 128] = sL[tid + i * 128];
        }
        const uint4* wH = (const uint4*)g_wh;
        const uint4* wL = (const uint4*)g_wl;
        uint4* bH = (uint4*)(smem + SM_BH);
        uint4* bL = (uint4*)(smem + SM_BL);
#pragma unroll
        for (int i = 0; i < 4; i++) {
            bH[tid + i * 128] = wH[tid + i * 128];
            bL[tid + i * 128] = wL[tid + i * 128];
        }
    }
    __syncthreads();

    int w = tid >> 5, lane = tid & 31;
    int lr = (lane & 7) + ((lane >> 3) & 1) * 8;
    int lc = (lane >> 4) * 16;

    float acc[2][8][4];
#pragma unroll
    for (int mi = 0; mi < 2; mi++)
#pragma unroll
        for (int ni = 0; ni < 8; ni++)
#pragma unroll
            for (int q = 0; q < 4; q++) acc[mi][ni][q] = 0.f;

    const uint32_t aoff[3] = {SM_AH, SM_AL, SM_AH};
    const uint32_t boff[3] = {SM_BH, SM_BH, SM_BL};

#pragma unroll
    for (int pass = 0; pass < 3; pass++) {
        uint32_t Ab = sb + aoff[pass];
        uint32_t Bb = sb + boff[pass];
#pragma unroll
        for (int k = 0; k < 4; k++) {
            int cb = k * 32 + lc;
            uint32_t a[2][4];
#pragma unroll
            for (int mi = 0; mi < 2; mi++) {
                uint32_t row = w * 32 + mi * 16 + lr;
                ldsm4(a[mi], Ab + SW128(row * 128 + cb));
            }
            uint32_t b[4][4];
#pragma unroll
            for (int p = 0; p < 4; p++) {
                uint32_t row = p * 16 + lr;
                ldsm4(b[p], Bb + SW128(row * 128 + cb));
            }
#pragma unroll
            for (int mi = 0; mi < 2; mi++)
#pragma unroll
                for (int ni = 0; ni < 8; ni++)
                    mma16816(acc[mi][ni], a[mi],
                             b[ni >> 1][ni & 1], b[ni >> 1][2 + (ni & 1)]);
        }
    }

    // ---- epilogue: smem staging (pitch 132, conflict-free) -> STG.128 ----
    __syncthreads();
    float* so = (float*)smem;
    int g = lane >> 2, t4 = lane & 3;
#pragma unroll
    for (int mi = 0; mi < 2; mi++) {
        int n_lo = w * 32 + mi * 16 + g;
#pragma unroll
        for (int ni = 0; ni < 8; ni++) {
            int o0 = (ni << 3) + (t4 << 1);
            so[o0 * 132 + n_lo] = acc[mi][ni][0];
            so[(o0 + 1) * 132 + n_lo] = acc[mi][ni][1];
            so[o0 * 132 + n_lo + 8] = acc[mi][ni][2];
            so[(o0 + 1) * 132 + n_lo + 8] = acc[mi][ni][3];
        }
    }
    __syncthreads();

    int b = bt / T_DIM, tt = bt - b * T_DIM;
    const long long OSTRIDE = (long long)T_DIM * N_NODES;
    float* ob = out + ((long long)(b * OUT_DIM) * T_DIM + tt) * N_NODES + n0;
#pragma unroll
    for (int it = 0; it < 16; it++) {
        int idx = it * 128 + tid;
        int o = idx >> 5, q4 = idx & 31;
        float4 v = *(const float4*)&so[o * 132 + (q4 << 2)];
        float bb = __ldg(bias + o);
        v.x += bb; v.y += bb; v.z += bb; v.w += bb;
        *(float4*)(ob + (long long)o * OSTRIDE + (q4 << 2)) = v;
    }
}

// ---------------- launch ----------------
extern "C" void kernel_launch(void* const* d_in, const int* in_sizes, int n_in,
                              void* d_out, int out_size) {
    const float* nf   = (const float*)d_in[0];  // node_feats [B,C,T,N]
    const float* ef   = (const float*)d_in[1];  // edge_feat  [E,1,1,C]
    const int*   src  = (const int*)d_in[2];
    const int*   dst  = (const int*)d_in[3];
    const float* W    = (const float*)d_in[4];
    const float* bvec = (const float*)d_in[5];
    float* out = (float*)d_out;

    k_transpose<<<dim3(N_NODES / 32, C_DIM / 32, BT + 1), dim3(32, 8)>>>(nf, W, src, dst);
    k_msg<<<dim3(N_NODES, BT / MSG_BT), 256>>>(ef);
    k_gemm_mma<<<dim3(N_NODES / 128, BT), 128>>>(bvec, out);
}

// round 13
// speedup vs baseline: 1.0776x; 1.0776x over previous
#include <cuda_runtime.h>
#include <cuda_fp16.h>
#include <cstdint>

#define N_NODES 2048
#define N_EDGES 16384
#define B_DIM 8
#define C_DIM 64
#define T_DIM 12
#define BT 96                 // B*T
#define OUT_DIM 64

// ---------------- scratch (static __device__, no allocation) ----------------
__device__ __half g_hH[N_NODES * BT * C_DIM];    // h*log2e fp16 hi, [n][bt][c]
__device__ __half g_hL[N_NODES * BT * C_DIM];    // h*log2e fp16 lo (residual)
// feats pre-split to bf16 hi/lo, pre-SW128-swizzled per 128B row: [bt][n][128B]
__device__ __align__(16) uint8_t g_fh[BT * N_NODES * 128];
__device__ __align__(16) uint8_t g_fl[BT * N_NODES * 128];
// W^T pre-split bf16 hi/lo, pre-swizzled: [o][128B]
__device__ __align__(16) uint8_t g_wh[OUT_DIM * 128];
__device__ __align__(16) uint8_t g_wl[OUT_DIM * 128];
__device__ int   g_cnt[N_NODES];                 // zeroed by k_gemm_mma (post-msg)
__device__ int   g_epack[N_NODES * 64];          // (eid<<11)|src per dst slot

// ---------------- packed f32x2 helpers ----------------
union F2U { float2 f; unsigned long long u; };
__device__ __forceinline__ float2 f2add(float2 a, float2 b) {
    F2U A, B2, D; A.f = a; B2.f = b;
    asm("add.rn.f32x2 %0, %1, %2;" : "=l"(D.u) : "l"(A.u), "l"(B2.u));
    return D.f;
}
__device__ __forceinline__ float2 f2fma(float2 a, float2 b, float2 c) {
    F2U A, B2, C2, D; A.f = a; B2.f = b; C2.f = c;
    asm("fma.rn.f32x2 %0, %1, %2, %3;" : "=l"(D.u) : "l"(A.u), "l"(B2.u), "l"(C2.u));
    return D.f;
}
__device__ __forceinline__ float ex2f(float x) {
    float r; asm("ex2.approx.f32 %0, %1;" : "=f"(r) : "f"(x)); return r;
}
__device__ __forceinline__ float rcpf(float x) {
    float r; asm("rcp.approx.f32 %0, %1;" : "=f"(r) : "f"(x)); return r;
}
__device__ __forceinline__ uint32_t smem_u32(const void* p) {
    uint32_t a;
    asm("{ .reg .u64 t; cvta.to.shared.u64 t, %1; cvt.u32.u64 %0, t; }"
        : "=r"(a) : "l"(p));
    return a;
}
// split two fp32 into packed bf16x2 hi + lo (hi = rn(x), lo = rn(x - hi))
__device__ __forceinline__ void bf16_split2(float a, float b,
                                            uint32_t& hp, uint32_t& lp) {
    asm("cvt.rn.bf16x2.f32 %0, %1, %2;" : "=r"(hp) : "f"(b), "f"(a));
    float fa = __uint_as_float(hp << 16);
    float fb = __uint_as_float(hp & 0xffff0000u);
    float ra = a - fa, rb = b - fb;
    asm("cvt.rn.bf16x2.f32 %0, %1, %2;" : "=r"(lp) : "f"(rb), "f"(ra));
}
#define SW128(off) ((off) ^ (((off) >> 3) & 0x70))

// ---------------- stage A: transpose [B,C,T,N] -> [N,BT,C] (*log2e),
// stored as fp16 hi + fp16 lo. Extra z-slice: build buckets + W prep. --------
__global__ void k_transpose(const float* __restrict__ nf,
                            const float* __restrict__ W,
                            const int* __restrict__ src,
                            const int* __restrict__ dst) {
    if (blockIdx.z == BT) {
        int t = threadIdx.y * 32 + threadIdx.x;
        if (blockIdx.y == 0) {
            int e = blockIdx.x * 256 + t;      // 64 blocks x 256 = 16384
            int d = dst[e];
            int p = atomicAdd(&g_cnt[d], 1);
            g_epack[(d << 6) + p] = (e << 11) | src[e];
        } else if (blockIdx.x == 0) {
            for (int i = t; i < 2048; i += 256) {   // i = o*32 + cp
                int o = i >> 5, cp = i & 31;
                float w0 = W[(2 * cp) * 64 + o];
                float w1 = W[(2 * cp + 1) * 64 + o];
                uint32_t hp, lp;
                bf16_split2(w0, w1, hp, lp);
                uint32_t off = SW128((uint32_t)(o * 128 + cp * 4));
                *(uint32_t*)(g_wh + off) = hp;
                *(uint32_t*)(g_wl + off) = lp;
            }
        }
        return;
    }
    __shared__ float tile[32][33];
    const float LOG2E = 1.4426950408889634f;
    int bt = blockIdx.z;
    int b = bt / T_DIM, t = bt - b * T_DIM;
    int c0 = blockIdx.y << 5, n0 = blockIdx.x << 5;
    int tx = threadIdx.x, ty = threadIdx.y;
#pragma unroll
    for (int i = 0; i < 4; i++) {
        int c = c0 + ty + i * 8;
        tile[ty + i * 8][tx] =
            nf[(((b * C_DIM + c) * T_DIM + t) * N_NODES) + n0 + tx] * LOG2E;
    }
    __syncthreads();
#pragma unroll
    for (int i = 0; i < 4; i++) {
        int n = n0 + ty + i * 8;
        float v = tile[tx][ty + i * 8];
        int idx = ((n * BT + bt) << 6) + c0 + tx;
        __half hv = __float2half_rn(v);
        g_hH[idx] = hv;
        g_hL[idx] = __float2half_rn(v - __half2float(hv));
    }
}

// ---------------- stage B: message + softmax + agg + residual ---------------
// grid (N_NODES, 3), block 256: co = tid&7 (c-octet), grp = tid>>3 (32 bt).
// h gathered fp16 hi; residual reconstructed from fp16 hi+lo; accum fp32.
#define MSG_BT 32
__global__ __launch_bounds__(256) void k_msg(const float* __restrict__ ef) {
    __shared__ __align__(16) float s_ev[64 * 64];
    __shared__ int s_ep[64];
    __shared__ int s_cnt;
    int n = blockIdx.x;
    int tid = threadIdx.x;
    if (tid == 0) s_cnt = g_cnt[n];
    if (tid < 64) s_ep[tid] = g_epack[(n << 6) + tid];
    __syncthreads();
    int cnt = s_cnt;
    const float LOG2E = 1.4426950408889634f;
    for (int i = tid; i < (cnt << 6); i += 256) {
        int eid = s_ep[i >> 6] >> 11;
        s_ev[i] = ef[(eid << 6) + (i & 63)] * LOG2E;
    }
    __syncthreads();

    int co = tid & 7;             // c-octet: c = 8*co .. +7
    int grp = tid >> 3;           // bt slot 0..31
    int bt = blockIdx.y * MSG_BT + grp;

    float2 den[4], num[4];
#pragma unroll
    for (int i = 0; i < 4; i++) {
        den[i] = make_float2(0.f, 0.f);
        num[i] = make_float2(0.f, 0.f);
    }

    const float4* evp4 = (const float4*)s_ev;      // [edge][16 float4]
    const uint4* hb = (const uint4*)g_hH;          // row = 8 uint4 (64 halves)

#define PROC8(HV, EA, EB)                                                  \
    {                                                                      \
        float2 f0 = __half22float2(*(const __half2*)&(HV).x);              \
        float2 f1 = __half22float2(*(const __half2*)&(HV).y);              \
        float2 f2 = __half22float2(*(const __half2*)&(HV).z);              \
        float2 f3 = __half22float2(*(const __half2*)&(HV).w);              \
        float2 v0 = f2add(f0, make_float2((EA).x, (EA).y));                \
        float2 v1 = f2add(f1, make_float2((EA).z, (EA).w));                \
        float2 v2 = f2add(f2, make_float2((EB).x, (EB).y));                \
        float2 v3 = f2add(f3, make_float2((EB).z, (EB).w));                \
        float2 r0 = make_float2(fmaxf(v0.x, 0.f), fmaxf(v0.y, 0.f));       \
        float2 r1 = make_float2(fmaxf(v1.x, 0.f), fmaxf(v1.y, 0.f));       \
        float2 r2 = make_float2(fmaxf(v2.x, 0.f), fmaxf(v2.y, 0.f));       \
        float2 r3 = make_float2(fmaxf(v3.x, 0.f), fmaxf(v3.y, 0.f));       \
        float2 p0 = make_float2(ex2f(r0.x), ex2f(r0.y));                   \
        float2 p1 = make_float2(ex2f(r1.x), ex2f(r1.y));                   \
        float2 p2 = make_float2(ex2f(r2.x), ex2f(r2.y));                   \
        float2 p3 = make_float2(ex2f(r3.x), ex2f(r3.y));                   \
        den[0] = f2add(den[0], p0); num[0] = f2fma(r0, p0, num[0]);        \
        den[1] = f2add(den[1], p1); num[1] = f2fma(r1, p1, num[1]);        \
        den[2] = f2add(den[2], p2); num[2] = f2fma(r2, p2, num[2]);        \
        den[3] = f2add(den[3], p3); num[3] = f2fma(r3, p3, num[3]);        \
    }

    int k = 0;
    for (; k + 2 <= cnt; k += 2) {
        int s0 = s_ep[k] & 2047;
        int s1 = s_ep[k + 1] & 2047;
        uint4 hv0 = hb[(s0 * BT + bt) * 8 + co];
        uint4 hv1 = hb[(s1 * BT + bt) * 8 + co];
        float4 ea0 = evp4[(k << 4) + (co << 1)];
        float4 eb0 = evp4[(k << 4) + (co << 1) + 1];
        float4 ea1 = evp4[((k + 1) << 4) + (co << 1)];
        float4 eb1 = evp4[((k + 1) << 4) + (co << 1) + 1];
        PROC8(hv0, ea0, eb0);
        PROC8(hv1, ea1, eb1);
    }
    if (k < cnt) {
        int s0 = s_ep[k] & 2047;
        uint4 hv0 = hb[(s0 * BT + bt) * 8 + co];
        float4 ea0 = evp4[(k << 4) + (co << 1)];
        float4 eb0 = evp4[(k << 4) + (co << 1) + 1];
        PROC8(hv0, ea0, eb0);
    }
#undef PROC8

    const float LN2 = 0.6931471805599453f;
    const float EPS = 1e-7f;
    // residual h: reconstruct fp32 from fp16 hi+lo (err ~2.4e-7)
    uint4 hvH = hb[(n * BT + bt) * 8 + co];
    uint4 hvL = ((const uint4*)g_hL)[(n * BT + bt) * 8 + co];
    float2 hp[4];
    {
        const uint32_t* ph = &hvH.x;
        const uint32_t* pl = &hvL.x;
#pragma unroll
        for (int i = 0; i < 4; i++)
            hp[i] = f2add(__half22float2(*(const __half2*)&ph[i]),
                          __half22float2(*(const __half2*)&pl[i]));
    }

    uint32_t H[4], L[4];
    bool has = (cnt > 0);
#pragma unroll
    for (int i = 0; i < 4; i++) {
        float2 agg = make_float2(0.f, 0.f);
        if (has) {
            agg.x = fmaf(num[i].x * rcpf(den[i].x), LN2, EPS);
            agg.y = fmaf(num[i].y * rcpf(den[i].y), LN2, EPS);
        }
        float ox = fmaf(hp[i].x, LN2, agg.x);
        float oy = fmaf(hp[i].y, LN2, agg.y);
        bf16_split2(ox, oy, H[i], L[i]);
    }
    size_t base = ((size_t)bt * N_NODES + n) * 128 +
                  (((uint32_t)(co * 16)) ^ (((uint32_t)n & 7) << 4));
    *(uint4*)(g_fh + base) = make_uint4(H[0], H[1], H[2], H[3]);
    *(uint4*)(g_fl + base) = make_uint4(L[0], L[1], L[2], L[3]);
}

// ---------------- stage C: HMMA bf16 GEMM (mma.sync), out [B,O,T,N] ---------
// Single k-loop with operand reuse: per k load Ah,Al,Bh (8 ldsm.x4), do
// Ah*Bh + Al*Bh, then load Bl into the B regs (4 ldsm.x4) and do Ah*Bl.
// 12 ldsm.x4 per k vs 18 in the 3-pass form (-33% L1 wavefronts).
#define SM_AH 0
#define SM_AL 16384
#define SM_BH 32768
#define SM_BL 40960

__device__ __forceinline__ void ldsm4(uint32_t* r, uint32_t addr) {
    asm volatile("ldmatrix.sync.aligned.m8n8.x4.shared.b16 {%0,%1,%2,%3}, [%4];"
                 : "=r"(r[0]), "=r"(r[1]), "=r"(r[2]), "=r"(r[3]) : "r"(addr));
}
__device__ __forceinline__ void mma16816(float* d, const uint32_t* a,
                                         uint32_t b0, uint32_t b1) {
    asm volatile(
        "mma.sync.aligned.m16n8k16.row.col.f32.bf16.bf16.f32 "
        "{%0,%1,%2,%3}, {%4,%5,%6,%7}, {%8,%9}, {%0,%1,%2,%3};"
        : "+f"(d[0]), "+f"(d[1]), "+f"(d[2]), "+f"(d[3])
        : "r"(a[0]), "r"(a[1]), "r"(a[2]), "r"(a[3]), "r"(b0), "r"(b1));
}

__global__ __launch_bounds__(128) void k_gemm_mma(const float* __restrict__ bias,
                                                  float* __restrict__ out) {
    __shared__ __align__(1024) uint8_t smem[49152];
    uint32_t sb = smem_u32(smem);
    int tid = threadIdx.x;
    int bt = blockIdx.y;
    int n0 = blockIdx.x << 7;

    if (bt == 0) g_cnt[(blockIdx.x << 7) + tid] = 0;   // 16*128 = 2048

    // ---- prologue: pure coalesced copies (pre-swizzled in gmem) ----
    {
        const uint4* sH = (const uint4*)(g_fh + ((size_t)bt * N_NODES + n0) * 128);
        const uint4* sL = (const uint4*)(g_fl + ((size_t)bt * N_NODES + n0) * 128);
        uint4* dH = (uint4*)(smem + SM_AH);
        uint4* dL = (uint4*)(smem + SM_AL);
#pragma unroll
        for (int i = 0; i < 8; i++) {
            dH[tid + i * 128] = sH[tid + i * 128];
            dL[tid + i * 128] = sL[tid + i * 128];
        }
        const uint4* wH = (const uint4*)g_wh;
        const uint4* wL = (const uint4*)g_wl;
        uint4* bH = (uint4*)(smem + SM_BH);
        uint4* bL = (uint4*)(smem + SM_BL);
#pragma unroll
        for (int i = 0; i < 4; i++) {
            bH[tid + i * 128] = wH[tid + i * 128];
            bL[tid + i * 128] = wL[tid + i * 128];
        }
    }
    __syncthreads();

    int w = tid >> 5, lane = tid & 31;
    int lr = (lane & 7) + ((lane >> 3) & 1) * 8;
    int lc = (lane >> 4) * 16;

    float acc[2][8][4];
#pragma unroll
    for (int mi = 0; mi < 2; mi++)
#pragma unroll
        for (int ni = 0; ni < 8; ni++)
#pragma unroll
            for (int q = 0; q < 4; q++) acc[mi][ni][q] = 0.f;

#pragma unroll
    for (int k = 0; k < 4; k++) {
        int cb = k * 32 + lc;
        uint32_t aH[2][4], aL[2][4], bb[4][4];
#pragma unroll
        for (int mi = 0; mi < 2; mi++) {
            uint32_t row = w * 32 + mi * 16 + lr;
            ldsm4(aH[mi], sb + SM_AH + SW128(row * 128 + cb));
            ldsm4(aL[mi], sb + SM_AL + SW128(row * 128 + cb));
        }
#pragma unroll
        for (int p = 0; p < 4; p++) {
            uint32_t row = p * 16 + lr;
            ldsm4(bb[p], sb + SM_BH + SW128(row * 128 + cb));
        }
        // Ah*Bh + Al*Bh
#pragma unroll
        for (int mi = 0; mi < 2; mi++)
#pragma unroll
            for (int ni = 0; ni < 8; ni++) {
                mma16816(acc[mi][ni], aH[mi],
                         bb[ni >> 1][ni & 1], bb[ni >> 1][2 + (ni & 1)]);
                mma16816(acc[mi][ni], aL[mi],
                         bb[ni >> 1][ni & 1], bb[ni >> 1][2 + (ni & 1)]);
            }
        // reload B = Bl, then Ah*Bl
#pragma unroll
        for (int p = 0; p < 4; p++) {
            uint32_t row = p * 16 + lr;
            ldsm4(bb[p], sb + SM_BL + SW128(row * 128 + cb));
        }
#pragma unroll
        for (int mi = 0; mi < 2; mi++)
#pragma unroll
            for (int ni = 0; ni < 8; ni++)
                mma16816(acc[mi][ni], aH[mi],
                         bb[ni >> 1][ni & 1], bb[ni >> 1][2 + (ni & 1)]);
    }

    // ---- epilogue: smem staging (pitch 132, conflict-free) -> STG.128 ----
    __syncthreads();
    float* so = (float*)smem;
    int g = lane >> 2, t4 = lane & 3;
#pragma unroll
    for (int mi = 0; mi < 2; mi++) {
        int n_lo = w * 32 + mi * 16 + g;
#pragma unroll
        for (int ni = 0; ni < 8; ni++) {
            int o0 = (ni << 3) + (t4 << 1);
            so[o0 * 132 + n_lo] = acc[mi][ni][0];
            so[(o0 + 1) * 132 + n_lo] = acc[mi][ni][1];
            so[o0 * 132 + n_lo + 8] = acc[mi][ni][2];
            so[(o0 + 1) * 132 + n_lo + 8] = acc[mi][ni][3];
        }
    }
    __syncthreads();

    int b = bt / T_DIM, tt = bt - b * T_DIM;
    const long long OSTRIDE = (long long)T_DIM * N_NODES;
    float* ob = out + ((long long)(b * OUT_DIM) * T_DIM + tt) * N_NODES + n0;
#pragma unroll
    for (int it = 0; it < 16; it++) {
        int idx = it * 128 + tid;
        int o = idx >> 5, q4 = idx & 31;
        float4 v = *(const float4*)&so[o * 132 + (q4 << 2)];
        float bb = __ldg(bias + o);
        v.x += bb; v.y += bb; v.z += bb; v.w += bb;
        *(float4*)(ob + (long long)o * OSTRIDE + (q4 << 2)) = v;
    }
}

// ---------------- launch ----------------
extern "C" void kernel_launch(void* const* d_in, const int* in_sizes, int n_in,
                              void* d_out, int out_size) {
    const float* nf   = (const float*)d_in[0];  // node_feats [B,C,T,N]
    const float* ef   = (const float*)d_in[1];  // edge_feat  [E,1,1,C]
    const int*   src  = (const int*)d_in[2];
    const int*   dst  = (const int*)d_in[3];
    const float* W    = (const float*)d_in[4];
    const float* bvec = (const float*)d_in[5];
    float* out = (float*)d_out;

    k_transpose<<<dim3(N_NODES / 32, C_DIM / 32, BT + 1), dim3(32, 8)>>>(nf, W, src, dst);
    k_msg<<<dim3(N_NODES, BT / MSG_BT), 256>>>(ef);
    k_gemm_mma<<<dim3(N_NODES / 128, BT), 128>>>(bvec, out);
}

// round 15
// speedup vs baseline: 1.1309x; 1.0495x over previous
#include <cuda_runtime.h>
#include <cuda_fp16.h>
#include <cstdint>

#define N_NODES 2048
#define N_EDGES 16384
#define B_DIM 8
#define C_DIM 64
#define T_DIM 12
#define BT 96                 // B*T
#define OUT_DIM 64

// ---------------- scratch (static __device__, no allocation) ----------------
__device__ __half g_hH[N_NODES * BT * C_DIM];    // h*log2e fp16 hi, [n][bt][c]
__device__ __half g_hL[N_NODES * BT * C_DIM];    // h*log2e fp16 lo (residual)
// feats pre-split to bf16 hi/lo, pre-SW128-swizzled per 128B row: [bt][n][128B]
__device__ __align__(16) uint8_t g_fh[BT * N_NODES * 128];
__device__ __align__(16) uint8_t g_fl[BT * N_NODES * 128];
// W^T pre-split bf16 hi/lo, pre-swizzled: [o][128B]
__device__ __align__(16) uint8_t g_wh[OUT_DIM * 128];
__device__ __align__(16) uint8_t g_wl[OUT_DIM * 128];
__device__ int   g_cnt[N_NODES];                 // zeroed by k_gemm_mma (post-msg)
__device__ int   g_epack[N_NODES * 64];          // (eid<<11)|src per dst slot

// ---------------- packed f32x2 helpers ----------------
union F2U { float2 f; unsigned long long u; };
__device__ __forceinline__ float2 f2add(float2 a, float2 b) {
    F2U A, B2, D; A.f = a; B2.f = b;
    asm("add.rn.f32x2 %0, %1, %2;" : "=l"(D.u) : "l"(A.u), "l"(B2.u));
    return D.f;
}
__device__ __forceinline__ float2 f2fma(float2 a, float2 b, float2 c) {
    F2U A, B2, C2, D; A.f = a; B2.f = b; C2.f = c;
    asm("fma.rn.f32x2 %0, %1, %2, %3;" : "=l"(D.u) : "l"(A.u), "l"(B2.u), "l"(C2.u));
    return D.f;
}
__device__ __forceinline__ float rcpf(float x) {
    float r; asm("rcp.approx.f32 %0, %1;" : "=f"(r) : "f"(x)); return r;
}
__device__ __forceinline__ uint32_t smem_u32(const void* p) {
    uint32_t a;
    asm("{ .reg .u64 t; cvta.to.shared.u64 t, %1; cvt.u32.u64 %0, t; }"
        : "=r"(a) : "l"(p));
    return a;
}
// split two fp32 into packed bf16x2 hi + lo (hi = rn(x), lo = rn(x - hi))
__device__ __forceinline__ void bf16_split2(float a, float b,
                                            uint32_t& hp, uint32_t& lp) {
    asm("cvt.rn.bf16x2.f32 %0, %1, %2;" : "=r"(hp) : "f"(b), "f"(a));
    float fa = __uint_as_float(hp << 16);
    float fb = __uint_as_float(hp & 0xffff0000u);
    float ra = a - fa, rb = b - fb;
    asm("cvt.rn.bf16x2.f32 %0, %1, %2;" : "=r"(lp) : "f"(rb), "f"(ra));
}
__device__ __forceinline__ __half2 hex2(__half2 x) {
    uint32_t xi = *(uint32_t*)&x, d;
    asm("ex2.approx.f16x2 %0, %1;" : "=r"(d) : "r"(xi));
    return *(__half2*)&d;
}
#define SW128(off) ((off) ^ (((off) >> 3) & 0x70))

// ---------------- stage A: transpose [B,C,T,N] -> [N,BT,C] (*log2e),
// stored fp16 hi + fp16 lo, packed half2 stores. Extra z-slice: buckets + W. -
__global__ void k_transpose(const float* __restrict__ nf,
                            const float* __restrict__ W,
                            const int* __restrict__ src,
                            const int* __restrict__ dst) {
    if (blockIdx.z == BT) {
        int t = threadIdx.y * 32 + threadIdx.x;
        if (blockIdx.y == 0) {
            int e = blockIdx.x * 256 + t;      // 64 blocks x 256 = 16384
            int d = dst[e];
            int p = atomicAdd(&g_cnt[d], 1);
            g_epack[(d << 6) + p] = (e << 11) | src[e];
        } else if (blockIdx.x == 0) {
            for (int i = t; i < 2048; i += 256) {   // i = o*32 + cp
                int o = i >> 5, cp = i & 31;
                float w0 = W[(2 * cp) * 64 + o];
                float w1 = W[(2 * cp + 1) * 64 + o];
                uint32_t hp, lp;
                bf16_split2(w0, w1, hp, lp);
                uint32_t off = SW128((uint32_t)(o * 128 + cp * 4));
                *(uint32_t*)(g_wh + off) = hp;
                *(uint32_t*)(g_wl + off) = lp;
            }
        }
        return;
    }
    __shared__ float tile[32][33];   // [n-in-block][c-in-block], pitch 33
    const float LOG2E = 1.4426950408889634f;
    int bt = blockIdx.z;
    int b = bt / T_DIM, t = bt - b * T_DIM;
    int c0 = blockIdx.y << 5, n0 = blockIdx.x << 5;
    int tx = threadIdx.x, ty = threadIdx.y;
#pragma unroll
    for (int i = 0; i < 4; i++) {
        int c = c0 + ty + i * 8;
        tile[tx][ty + i * 8] =
            nf[(((b * C_DIM + c) * T_DIM + t) * N_NODES) + n0 + tx] * LOG2E;
    }
    __syncthreads();
    int cp = tx & 15, hf = tx >> 4;
#pragma unroll
    for (int i = 0; i < 2; i++) {
        int ni = ty + hf * 8 + i * 16;
        // scalar LDS.32 pair (pitch-33 rows are only 4B aligned)
        float vx = tile[ni][2 * cp];
        float vy = tile[ni][2 * cp + 1];
        __half2 hi2 = __floats2half2_rn(vx, vy);
        float2 hif = __half22float2(hi2);
        __half2 lo2 = __floats2half2_rn(vx - hif.x, vy - hif.y);
        int n = n0 + ni;
        int idx = (((n * BT + bt) << 6) + c0 + 2 * cp);
        *(__half2*)&g_hH[idx] = hi2;
        *(__half2*)&g_hL[idx] = lo2;
    }
}

// ---------------- stage B: message + softmax + agg + residual ---------------
// grid (N_NODES, 3), block 256: co = tid&7 (c-octet), grp = tid>>3 (32 bt).
// h, e, relu, exp all in f16x2 (MUFU halved); den/num accumulate in fp32.
#define MSG_BT 32
__global__ __launch_bounds__(256) void k_msg(const float* __restrict__ ef) {
    __shared__ __align__(16) __half s_ev[64 * 64];
    __shared__ int s_ep[64];
    __shared__ int s_cnt;
    int n = blockIdx.x;
    int tid = threadIdx.x;
    if (tid == 0) s_cnt = g_cnt[n];
    if (tid < 64) s_ep[tid] = g_epack[(n << 6) + tid];
    __syncthreads();
    int cnt = s_cnt;
    const float LOG2E = 1.4426950408889634f;
    for (int i = tid; i < (cnt << 6); i += 256) {
        int eid = s_ep[i >> 6] >> 11;
        s_ev[i] = __float2half_rn(ef[(eid << 6) + (i & 63)] * LOG2E);
    }
    __syncthreads();

    int co = tid & 7;             // c-octet: c = 8*co .. +7
    int grp = tid >> 3;           // bt slot 0..31
    int bt = blockIdx.y * MSG_BT + grp;

    float2 den[4], num[4];
#pragma unroll
    for (int i = 0; i < 4; i++) {
        den[i] = make_float2(0.f, 0.f);
        num[i] = make_float2(0.f, 0.f);
    }

    const uint4* evp = (const uint4*)s_ev;         // [edge][8 x half2-quad]
    const uint4* hb = (const uint4*)g_hH;          // row = 8 uint4 (64 halves)
    const __half2 Z2 = __float2half2_rn(0.f);

#define PROC8(HV, EV)                                                      \
    {                                                                      \
        const __half2* hh = (const __half2*)&(HV);                         \
        const __half2* ee = (const __half2*)&(EV);                         \
        _Pragma("unroll")                                                  \
        for (int j = 0; j < 4; j++) {                                      \
            __half2 r2 = __hmax2(__hadd2(hh[j], ee[j]), Z2);               \
            __half2 p2 = hex2(r2);                                         \
            float2 rf = __half22float2(r2);                                \
            float2 pf = __half22float2(p2);                                \
            den[j] = f2add(den[j], pf);                                    \
            num[j] = f2fma(rf, pf, num[j]);                                \
        }                                                                  \
    }

    int k = 0;
    for (; k + 2 <= cnt; k += 2) {
        int s0 = s_ep[k] & 2047;
        int s1 = s_ep[k + 1] & 2047;
        uint4 hv0 = hb[(s0 * BT + bt) * 8 + co];
        uint4 hv1 = hb[(s1 * BT + bt) * 8 + co];
        uint4 ev0 = evp[(k << 3) + co];
        uint4 ev1 = evp[((k + 1) << 3) + co];
        PROC8(hv0, ev0);
        PROC8(hv1, ev1);
    }
    if (k < cnt) {
        int s0 = s_ep[k] & 2047;
        uint4 hv0 = hb[(s0 * BT + bt) * 8 + co];
        uint4 ev0 = evp[(k << 3) + co];
        PROC8(hv0, ev0);
    }
#undef PROC8

    const float LN2 = 0.6931471805599453f;
    const float EPS = 1e-7f;
    // residual h: reconstruct fp32 from fp16 hi+lo (err ~2.4e-7)
    uint4 hvH = hb[(n * BT + bt) * 8 + co];
    uint4 hvL = ((const uint4*)g_hL)[(n * BT + bt) * 8 + co];
    float2 hp[4];
    {
        const uint32_t* ph = &hvH.x;
        const uint32_t* pl = &hvL.x;
#pragma unroll
        for (int i = 0; i < 4; i++)
            hp[i] = f2add(__half22float2(*(const __half2*)&ph[i]),
                          __half22float2(*(const __half2*)&pl[i]));
    }

    uint32_t H[4], L[4];
    bool has = (cnt > 0);
#pragma unroll
    for (int i = 0; i < 4; i++) {
        float2 agg = make_float2(0.f, 0.f);
        if (has) {
            agg.x = fmaf(num[i].x * rcpf(den[i].x), LN2, EPS);
            agg.y = fmaf(num[i].y * rcpf(den[i].y), LN2, EPS);
        }
        float ox = fmaf(hp[i].x, LN2, agg.x);
        float oy = fmaf(hp[i].y, LN2, agg.y);
        bf16_split2(ox, oy, H[i], L[i]);
    }
    size_t base = ((size_t)bt * N_NODES + n) * 128 +
                  (((uint32_t)(co * 16)) ^ (((uint32_t)n & 7) << 4));
    *(uint4*)(g_fh + base) = make_uint4(H[0], H[1], H[2], H[3]);
    *(uint4*)(g_fl + base) = make_uint4(L[0], L[1], L[2], L[3]);
}

// ---------------- stage C: HMMA bf16 GEMM (mma.sync), out [B,O,T,N] ---------
// Single k-loop with operand reuse: per k load Ah,Al,Bh (8 ldsm.x4), do
// Ah*Bh + Al*Bh, then load Bl (4 ldsm.x4) and do Ah*Bl.
#define SM_AH 0
#define SM_AL 16384
#define SM_BH 32768
#define SM_BL 40960

__device__ __forceinline__ void ldsm4(uint32_t* r, uint32_t addr) {
    asm volatile("ldmatrix.sync.aligned.m8n8.x4.shared.b16 {%0,%1,%2,%3}, [%4];"
                 : "=r"(r[0]), "=r"(r[1]), "=r"(r[2]), "=r"(r[3]) : "r"(addr));
}
__device__ __forceinline__ void mma16816(float* d, const uint32_t* a,
                                         uint32_t b0, uint32_t b1) {
    asm volatile(
        "mma.sync.aligned.m16n8k16.row.col.f32.bf16.bf16.f32 "
        "{%0,%1,%2,%3}, {%4,%5,%6,%7}, {%8,%9}, {%0,%1,%2,%3};"
        : "+f"(d[0]), "+f"(d[1]), "+f"(d[2]), "+f"(d[3])
        : "r"(a[0]), "r"(a[1]), "r"(a[2]), "r"(a[3]), "r"(b0), "r"(b1));
}

__global__ __launch_bounds__(128) void k_gemm_mma(const float* __restrict__ bias,
                                                  float* __restrict__ out) {
    __shared__ __align__(1024) uint8_t smem[49152];
    uint32_t sb = smem_u32(smem);
    int tid = threadIdx.x;
    int bt = blockIdx.y;
    int n0 = blockIdx.x << 7;

    if (bt == 0) g_cnt[(blockIdx.x << 7) + tid] = 0;   // 16*128 = 2048

    // ---- prologue: pure coalesced copies (pre-swizzled in gmem) ----
    {
        const uint4* sH = (const uint4*)(g_fh + ((size_t)bt * N_NODES + n0) * 128);
        const uint4* sL = (const uint4*)(g_fl + ((size_t)bt * N_NODES + n0) * 128);
        uint4* dH = (uint4*)(smem + SM_AH);
        uint4* dL = (uint4*)(smem + SM_AL);
#pragma unroll
        for (int i = 0; i < 8; i++) {
            dH[tid + i * 128] = sH[tid + i * 128];
            dL[tid + i * 128] = sL[tid + i * 128];
        }
        const uint4* wH = (const uint4*)g_wh;
        const uint4* wL = (const uint4*)g_wl;
        uint4* bH = (uint4*)(smem + SM_BH);
        uint4* bL = (uint4*)(smem + SM_BL);
#pragma unroll
        for (int i = 0; i < 4; i++) {
            bH[tid + i * 128] = wH[tid + i * 128];
            bL[tid + i * 128] = wL[tid + i * 128];
        }
    }
    __syncthreads();

    int w = tid >> 5, lane = tid & 31;
    int lr = (lane & 7) + ((lane >> 3) & 1) * 8;
    int lc = (lane >> 4) * 16;

    float acc[2][8][4];
#pragma unroll
    for (int mi = 0; mi < 2; mi++)
#pragma unroll
        for (int ni = 0; ni < 8; ni++)
#pragma unroll
            for (int q = 0; q < 4; q++) acc[mi][ni][q] = 0.f;

#pragma unroll
    for (int k = 0; k < 4; k++) {
        int cb = k * 32 + lc;
        uint32_t aH[2][4], aL[2][4], bb[4][4];
#pragma unroll
        for (int mi = 0; mi < 2; mi++) {
            uint32_t row = w * 32 + mi * 16 + lr;
            ldsm4(aH[mi], sb + SM_AH + SW128(row * 128 + cb));
            ldsm4(aL[mi], sb + SM_AL + SW128(row * 128 + cb));
        }
#pragma unroll
        for (int p = 0; p < 4; p++) {
            uint32_t row = p * 16 + lr;
            ldsm4(bb[p], sb + SM_BH + SW128(row * 128 + cb));
        }
#pragma unroll
        for (int mi = 0; mi < 2; mi++)
#pragma unroll
            for (int ni = 0; ni < 8; ni++) {
                mma16816(acc[mi][ni], aH[mi],
                         bb[ni >> 1][ni & 1], bb[ni >> 1][2 + (ni & 1)]);
                mma16816(acc[mi][ni], aL[mi],
                         bb[ni >> 1][ni & 1], bb[ni >> 1][2 + (ni & 1)]);
            }
#pragma unroll
        for (int p = 0; p < 4; p++) {
            uint32_t row = p * 16 + lr;
            ldsm4(bb[p], sb + SM_BL + SW128(row * 128 + cb));
        }
#pragma unroll
        for (int mi = 0; mi < 2; mi++)
#pragma unroll
            for (int ni = 0; ni < 8; ni++)
                mma16816(acc[mi][ni], aH[mi],
                         bb[ni >> 1][ni & 1], bb[ni >> 1][2 + (ni & 1)]);
    }

    // ---- epilogue: smem staging (pitch 132, conflict-free) -> STG.128 ----
    __syncthreads();
    float* so = (float*)smem;
    int g = lane >> 2, t4 = lane & 3;
#pragma unroll
    for (int mi = 0; mi < 2; mi++) {
        int n_lo = w * 32 + mi * 16 + g;
#pragma unroll
        for (int ni = 0; ni < 8; ni++) {
            int o0 = (ni << 3) + (t4 << 1);
            so[o0 * 132 + n_lo] = acc[mi][ni][0];
            so[(o0 + 1) * 132 + n_lo] = acc[mi][ni][1];
            so[o0 * 132 + n_lo + 8] = acc[mi][ni][2];
            so[(o0 + 1) * 132 + n_lo + 8] = acc[mi][ni][3];
        }
    }
    __syncthreads();

    int b = bt / T_DIM, tt = bt - b * T_DIM;
    const long long OSTRIDE = (long long)T_DIM * N_NODES;
    float* ob = out + ((long long)(b * OUT_DIM) * T_DIM + tt) * N_NODES + n0;
#pragma unroll
    for (int it = 0; it < 16; it++) {
        int idx = it * 128 + tid;
        int o = idx >> 5, q4 = idx & 31;
        float4 v = *(const float4*)&so[o * 132 + (q4 << 2)];
        float bb = __ldg(bias + o);
        v.x += bb; v.y += bb; v.z += bb; v.w += bb;
        *(float4*)(ob + (long long)o * OSTRIDE + (q4 << 2)) = v;
    }
}

// ---------------- launch ----------------
extern "C" void kernel_launch(void* const* d_in, const int* in_sizes, int n_in,
                              void* d_out, int out_size) {
    const float* nf   = (const float*)d_in[0];  // node_feats [B,C,T,N]
    const float* ef   = (const float*)d_in[1];  // edge_feat  [E,1,1,C]
    const int*   src  = (const int*)d_in[2];
    const int*   dst  = (const int*)d_in[3];
    const float* W    = (const float*)d_in[4];
    const float* bvec = (const float*)d_in[5];
    float* out = (float*)d_out;

    k_transpose<<<dim3(N_NODES / 32, C_DIM / 32, BT + 1), dim3(32, 8)>>>(nf, W, src, dst);
    k_msg<<<dim3(N_NODES, BT / MSG_BT), 256>>>(ef);
    k_gemm_mma<<<dim3(N_NODES / 128, BT), 128>>>(bvec, out);
}

// round 16
// speedup vs baseline: 1.2884x; 1.1393x over previous
#include <cuda_runtime.h>
#include <cuda_fp16.h>
#include <cstdint>

#define N_NODES 2048
#define N_EDGES 16384
#define B_DIM 8
#define C_DIM 64
#define T_DIM 12
#define BT 96                 // B*T
#define OUT_DIM 64

// ---------------- scratch (static __device__, no allocation) ----------------
__device__ __half g_hH[N_NODES * BT * C_DIM];    // h*log2e fp16, [n][bt][c]
// feats as fp16, pre-SW128-swizzled per 128B row: [bt][n][128B]
__device__ __align__(16) uint8_t g_fh[BT * N_NODES * 128];
// W^T fp16 hi/lo, pre-swizzled: [o][128B]
__device__ __align__(16) uint8_t g_wh[OUT_DIM * 128];
__device__ __align__(16) uint8_t g_wl[OUT_DIM * 128];
__device__ int   g_cnt[N_NODES];                 // zeroed by k_gemm_mma (post-msg)
__device__ int   g_epack[N_NODES * 64];          // (eid<<11)|src per dst slot

// ---------------- packed f32x2 helpers ----------------
union F2U { float2 f; unsigned long long u; };
__device__ __forceinline__ float2 f2add(float2 a, float2 b) {
    F2U A, B2, D; A.f = a; B2.f = b;
    asm("add.rn.f32x2 %0, %1, %2;" : "=l"(D.u) : "l"(A.u), "l"(B2.u));
    return D.f;
}
__device__ __forceinline__ float2 f2fma(float2 a, float2 b, float2 c) {
    F2U A, B2, C2, D; A.f = a; B2.f = b; C2.f = c;
    asm("fma.rn.f32x2 %0, %1, %2, %3;" : "=l"(D.u) : "l"(A.u), "l"(B2.u), "l"(C2.u));
    return D.f;
}
__device__ __forceinline__ float rcpf(float x) {
    float r; asm("rcp.approx.f32 %0, %1;" : "=f"(r) : "f"(x)); return r;
}
__device__ __forceinline__ uint32_t smem_u32(const void* p) {
    uint32_t a;
    asm("{ .reg .u64 t; cvta.to.shared.u64 t, %1; cvt.u32.u64 %0, t; }"
        : "=r"(a) : "l"(p));
    return a;
}
__device__ __forceinline__ __half2 hex2(__half2 x) {
    uint32_t xi = *(uint32_t*)&x, d;
    asm("ex2.approx.f16x2 %0, %1;" : "=r"(d) : "r"(xi));
    return *(__half2*)&d;
}
#define SW128(off) ((off) ^ (((off) >> 3) & 0x70))

// ---------------- stage A: transpose [B,C,T,N] -> [N,BT,C] (*log2e) fp16.
// Extra z-slice: by==0 edge buckets; by==1,bx==0 W fp16 hi/lo prep. ----------
__global__ void k_transpose(const float* __restrict__ nf,
                            const float* __restrict__ W,
                            const int* __restrict__ src,
                            const int* __restrict__ dst) {
    if (blockIdx.z == BT) {
        int t = threadIdx.y * 32 + threadIdx.x;
        if (blockIdx.y == 0) {
            int e = blockIdx.x * 256 + t;      // 64 blocks x 256 = 16384
            int d = dst[e];
            int p = atomicAdd(&g_cnt[d], 1);
            g_epack[(d << 6) + p] = (e << 11) | src[e];
        } else if (blockIdx.x == 0) {
            for (int i = t; i < 2048; i += 256) {   // i = o*32 + cp
                int o = i >> 5, cp = i & 31;
                float w0 = W[(2 * cp) * 64 + o];
                float w1 = W[(2 * cp + 1) * 64 + o];
                __half2 hi2 = __floats2half2_rn(w0, w1);
                float2 hif = __half22float2(hi2);
                __half2 lo2 = __floats2half2_rn(w0 - hif.x, w1 - hif.y);
                uint32_t off = SW128((uint32_t)(o * 128 + cp * 4));
                *(__half2*)(g_wh + off) = hi2;
                *(__half2*)(g_wl + off) = lo2;
            }
        }
        return;
    }
    __shared__ float tile[32][33];   // [n-in-block][c-in-block], pitch 33
    const float LOG2E = 1.4426950408889634f;
    int bt = blockIdx.z;
    int b = bt / T_DIM, t = bt - b * T_DIM;
    int c0 = blockIdx.y << 5, n0 = blockIdx.x << 5;
    int tx = threadIdx.x, ty = threadIdx.y;
#pragma unroll
    for (int i = 0; i < 4; i++) {
        int c = c0 + ty + i * 8;
        tile[tx][ty + i * 8] =
            nf[(((b * C_DIM + c) * T_DIM + t) * N_NODES) + n0 + tx] * LOG2E;
    }
    __syncthreads();
    int cp = tx & 15, hf = tx >> 4;
#pragma unroll
    for (int i = 0; i < 2; i++) {
        int ni = ty + hf * 8 + i * 16;
        float vx = tile[ni][2 * cp];
        float vy = tile[ni][2 * cp + 1];
        __half2 hi2 = __floats2half2_rn(vx, vy);
        int n = n0 + ni;
        int idx = (((n * BT + bt) << 6) + c0 + 2 * cp);
        *(__half2*)&g_hH[idx] = hi2;
    }
}

// ---------------- stage B: message + softmax + agg + residual ---------------
// grid (N_NODES, 3), block 256: co = tid&7 (c-octet), grp = tid>>3 (32 bt).
// h, e, relu, exp in f16x2; den/num accumulate fp32; feats stored fp16.
#define MSG_BT 32
__global__ __launch_bounds__(256) void k_msg(const float* __restrict__ ef) {
    __shared__ __align__(16) __half s_ev[64 * 64];
    __shared__ int s_ep[64];
    __shared__ int s_cnt;
    int n = blockIdx.x;
    int tid = threadIdx.x;
    if (tid == 0) s_cnt = g_cnt[n];
    if (tid < 64) s_ep[tid] = g_epack[(n << 6) + tid];
    __syncthreads();
    int cnt = s_cnt;
    const float LOG2E = 1.4426950408889634f;
    for (int i = tid; i < (cnt << 6); i += 256) {
        int eid = s_ep[i >> 6] >> 11;
        s_ev[i] = __float2half_rn(ef[(eid << 6) + (i & 63)] * LOG2E);
    }
    __syncthreads();

    int co = tid & 7;             // c-octet: c = 8*co .. +7
    int grp = tid >> 3;           // bt slot 0..31
    int bt = blockIdx.y * MSG_BT + grp;

    float2 den[4], num[4];
#pragma unroll
    for (int i = 0; i < 4; i++) {
        den[i] = make_float2(0.f, 0.f);
        num[i] = make_float2(0.f, 0.f);
    }

    const uint4* evp = (const uint4*)s_ev;         // [edge][8 x half2-quad]
    const uint4* hb = (const uint4*)g_hH;          // row = 8 uint4 (64 halves)
    const __half2 Z2 = __float2half2_rn(0.f);

#define PROC8(HV, EV)                                                      \
    {                                                                      \
        const __half2* hh = (const __half2*)&(HV);                         \
        const __half2* ee = (const __half2*)&(EV);                         \
        _Pragma("unroll")                                                  \
        for (int j = 0; j < 4; j++) {                                      \
            __half2 r2 = __hmax2(__hadd2(hh[j], ee[j]), Z2);               \
            __half2 p2 = hex2(r2);                                         \
            float2 rf = __half22float2(r2);                                \
            float2 pf = __half22float2(p2);                                \
            den[j] = f2add(den[j], pf);                                    \
            num[j] = f2fma(rf, pf, num[j]);                                \
        }                                                                  \
    }

    int k = 0;
    for (; k + 2 <= cnt; k += 2) {
        int s0 = s_ep[k] & 2047;
        int s1 = s_ep[k + 1] & 2047;
        uint4 hv0 = hb[(s0 * BT + bt) * 8 + co];
        uint4 hv1 = hb[(s1 * BT + bt) * 8 + co];
        uint4 ev0 = evp[(k << 3) + co];
        uint4 ev1 = evp[((k + 1) << 3) + co];
        PROC8(hv0, ev0);
        PROC8(hv1, ev1);
    }
    if (k < cnt) {
        int s0 = s_ep[k] & 2047;
        uint4 hv0 = hb[(s0 * BT + bt) * 8 + co];
        uint4 ev0 = evp[(k << 3) + co];
        PROC8(hv0, ev0);
    }
#undef PROC8

    const float LN2 = 0.6931471805599453f;
    const float EPS = 1e-7f;
    // residual h from fp16 (adds ~2.4e-4 incoherent error)
    uint4 hvH = hb[(n * BT + bt) * 8 + co];
    float2 hp[4];
    {
        const uint32_t* ph = &hvH.x;
#pragma unroll
        for (int i = 0; i < 4; i++)
            hp[i] = __half22float2(*(const __half2*)&ph[i]);
    }

    uint32_t H[4];
    bool has = (cnt > 0);
#pragma unroll
    for (int i = 0; i < 4; i++) {
        float2 agg = make_float2(0.f, 0.f);
        if (has) {
            agg.x = fmaf(num[i].x * rcpf(den[i].x), LN2, EPS);
            agg.y = fmaf(num[i].y * rcpf(den[i].y), LN2, EPS);
        }
        float ox = fmaf(hp[i].x, LN2, agg.x);
        float oy = fmaf(hp[i].y, LN2, agg.y);
        __half2 o2 = __floats2half2_rn(ox, oy);
        H[i] = *(uint32_t*)&o2;
    }
    size_t base = ((size_t)bt * N_NODES + n) * 128 +
                  (((uint32_t)(co * 16)) ^ (((uint32_t)n & 7) << 4));
    *(uint4*)(g_fh + base) = make_uint4(H[0], H[1], H[2], H[3]);
}

// ---------------- stage C: HMMA fp16 GEMM (mma.sync), out [B,O,T,N] ---------
// D = A*Wh + A*Wl (A fp16 feats; W split fp16 hi/lo so W error ~2^-24).
#define SM_AH 0
#define SM_BH 16384
#define SM_BL 24576

__device__ __forceinline__ void ldsm4(uint32_t* r, uint32_t addr) {
    asm volatile("ldmatrix.sync.aligned.m8n8.x4.shared.b16 {%0,%1,%2,%3}, [%4];"
                 : "=r"(r[0]), "=r"(r[1]), "=r"(r[2]), "=r"(r[3]) : "r"(addr));
}
__device__ __forceinline__ void mma16816(float* d, const uint32_t* a,
                                         uint32_t b0, uint32_t b1) {
    asm volatile(
        "mma.sync.aligned.m16n8k16.row.col.f32.f16.f16.f32 "
        "{%0,%1,%2,%3}, {%4,%5,%6,%7}, {%8,%9}, {%0,%1,%2,%3};"
        : "+f"(d[0]), "+f"(d[1]), "+f"(d[2]), "+f"(d[3])
        : "r"(a[0]), "r"(a[1]), "r"(a[2]), "r"(a[3]), "r"(b0), "r"(b1));
}

__global__ __launch_bounds__(128) void k_gemm_mma(const float* __restrict__ bias,
                                                  float* __restrict__ out) {
    __shared__ __align__(1024) uint8_t smem[34816];
    uint32_t sb = smem_u32(smem);
    int tid = threadIdx.x;
    int bt = blockIdx.y;
    int n0 = blockIdx.x << 7;

    if (bt == 0) g_cnt[(blockIdx.x << 7) + tid] = 0;   // 16*128 = 2048

    // ---- prologue: pure coalesced copies (pre-swizzled in gmem) ----
    {
        const uint4* sA = (const uint4*)(g_fh + ((size_t)bt * N_NODES + n0) * 128);
        uint4* dA = (uint4*)(smem + SM_AH);
#pragma unroll
        for (int i = 0; i < 8; i++) dA[tid + i * 128] = sA[tid + i * 128];
        const uint4* wH = (const uint4*)g_wh;
        const uint4* wL = (const uint4*)g_wl;
        uint4* bH = (uint4*)(smem + SM_BH);
        uint4* bL = (uint4*)(smem + SM_BL);
#pragma unroll
        for (int i = 0; i < 4; i++) {
            bH[tid + i * 128] = wH[tid + i * 128];
            bL[tid + i * 128] = wL[tid + i * 128];
        }
    }
    __syncthreads();

    int w = tid >> 5, lane = tid & 31;
    int lr = (lane & 7) + ((lane >> 3) & 1) * 8;
    int lc = (lane >> 4) * 16;

    float acc[2][8][4];
#pragma unroll
    for (int mi = 0; mi < 2; mi++)
#pragma unroll
        for (int ni = 0; ni < 8; ni++)
#pragma unroll
            for (int q = 0; q < 4; q++) acc[mi][ni][q] = 0.f;

#pragma unroll
    for (int k = 0; k < 4; k++) {
        int cb = k * 32 + lc;
        uint32_t aH[2][4], bb[4][4];
#pragma unroll
        for (int mi = 0; mi < 2; mi++) {
            uint32_t row = w * 32 + mi * 16 + lr;
            ldsm4(aH[mi], sb + SM_AH + SW128(row * 128 + cb));
        }
#pragma unroll
        for (int p = 0; p < 4; p++) {
            uint32_t row = p * 16 + lr;
            ldsm4(bb[p], sb + SM_BH + SW128(row * 128 + cb));
        }
#pragma unroll
        for (int mi = 0; mi < 2; mi++)
#pragma unroll
            for (int ni = 0; ni < 8; ni++)
                mma16816(acc[mi][ni], aH[mi],
                         bb[ni >> 1][ni & 1], bb[ni >> 1][2 + (ni & 1)]);
#pragma unroll
        for (int p = 0; p < 4; p++) {
            uint32_t row = p * 16 + lr;
            ldsm4(bb[p], sb + SM_BL + SW128(row * 128 + cb));
        }
#pragma unroll
        for (int mi = 0; mi < 2; mi++)
#pragma unroll
            for (int ni = 0; ni < 8; ni++)
                mma16816(acc[mi][ni], aH[mi],
                         bb[ni >> 1][ni & 1], bb[ni >> 1][2 + (ni & 1)]);
    }

    // ---- epilogue: smem staging (pitch 132, conflict-free) -> STG.128 ----
    __syncthreads();
    float* so = (float*)smem;   // 64*132*4 = 33792 <= 34816
    int g = lane >> 2, t4 = lane & 3;
#pragma unroll
    for (int mi = 0; mi < 2; mi++) {
        int n_lo = w * 32 + mi * 16 + g;
#pragma unroll
        for (int ni = 0; ni < 8; ni++) {
            int o0 = (ni << 3) + (t4 << 1);
            so[o0 * 132 + n_lo] = acc[mi][ni][0];
            so[(o0 + 1) * 132 + n_lo] = acc[mi][ni][1];
            so[o0 * 132 + n_lo + 8] = acc[mi][ni][2];
            so[(o0 + 1) * 132 + n_lo + 8] = acc[mi][ni][3];
        }
    }
    __syncthreads();

    int b = bt / T_DIM, tt = bt - b * T_DIM;
    const long long OSTRIDE = (long long)T_DIM * N_NODES;
    float* ob = out + ((long long)(b * OUT_DIM) * T_DIM + tt) * N_NODES + n0;
#pragma unroll
    for (int it = 0; it < 16; it++) {
        int idx = it * 128 + tid;
        int o = idx >> 5, q4 = idx & 31;
        float4 v = *(const float4*)&so[o * 132 + (q4 << 2)];
        float bb = __ldg(bias + o);
        v.x += bb; v.y += bb; v.z += bb; v.w += bb;
        *(float4*)(ob + (long long)o * OSTRIDE + (q4 << 2)) = v;
    }
}

// ---------------- launch ----------------
extern "C" void kernel_launch(void* const* d_in, const int* in_sizes, int n_in,
                              void* d_out, int out_size) {
    const float* nf   = (const float*)d_in[0];  // node_feats [B,C,T,N]
    const float* ef   = (const float*)d_in[1];  // edge_feat  [E,1,1,C]
    const int*   src  = (const int*)d_in[2];
    const int*   dst  = (const int*)d_in[3];
    const float* W    = (const float*)d_in[4];
    const float* bvec = (const float*)d_in[5];
    float* out = (float*)d_out;

    k_transpose<<<dim3(N_NODES / 32, C_DIM / 32, BT + 1), dim3(32, 8)>>>(nf, W, src, dst);
    k_msg<<<dim3(N_NODES, BT / MSG_BT), 256>>>(ef);
    k_gemm_mma<<<dim3(N_NODES / 128, BT), 128>>>(bvec, out);
}